// round 7
// baseline (speedup 1.0000x reference)
#include <cuda_runtime.h>
#include <math.h>

#define CIN      512
#define MAXB     131072
#define MAXTILES (MAXB / 32)     // 4096 tiles of 32 rows
#define NPRODB   512             // producer blocks (8 warps -> 8 tiles each)
#define NCONSB   148             // consumer blocks
#define NTAB     550             // 10+20+...+100 quadrature points
#define LOG2E    1.4426950408889634f
#define EPSQ     1e-5f

// Global scratch (static __device__: no allocation in kernel_launch).
__device__ float2       g_z[MAXB];
__device__ unsigned int g_flag[MAXTILES];   // 0 at every launch; producers set 1,
                                            // consumers reset to 0 after consuming

__device__ __forceinline__ float ex2f(float x) {
    float r;
    asm("ex2.approx.f32 %0, %1;" : "=f"(r) : "f"(x));
    return r;
}
__device__ __forceinline__ float dot4(float4 a, float4 b) {
    return fmaf(a.x, b.x, fmaf(a.y, b.y, fmaf(a.z, b.z, a.w * b.w)));
}

// ---------------------------------------------------------------------------
// Single kernel, two block roles, decoupled through L2 flags:
//   blocks [0, NPRODB)      : warp-per-tile dual GEMV (DRAM stream), release
//                             one flag per 32-row tile.
//   blocks [NPRODB, +NCONSB): warp-per-tile Beta quadrature (MUFU-bound),
//                             acquire flag, consume z, reset flag.
// Producers never wait on consumers (full-size scratch), and consumer blocks
// (148) < resident slots (592), so progress is always guaranteed. Consumer
// MUFU work (~17-20us) hides entirely under the ~40us DRAM stream.
// ---------------------------------------------------------------------------
__global__ void __launch_bounds__(256, 4)
beta_pipe(const float* __restrict__ x,
          const float* __restrict__ Wa, const float* __restrict__ ba,
          const float* __restrict__ Wb, const float* __restrict__ bb,
          float* __restrict__ out, int B)
{
    const int lane   = threadIdx.x & 31;
    const int wid    = threadIdx.x >> 5;
    const int ntiles = (B + 31) >> 5;

    if (blockIdx.x < NPRODB) {
        // ============================ producer ============================
        const int tile = blockIdx.x * 8 + wid;
        if (tile >= ntiles) return;

        const float4* wa4 = reinterpret_cast<const float4*>(Wa);
        const float4* wb4 = reinterpret_cast<const float4*>(Wb);
        const float biasa = ba[0], biasb = bb[0];
        const int rbase = tile << 5;
        const int rlim  = min(32, B - rbase);

        for (int r = 0; r < rlim; ++r) {
            const float4* xr = reinterpret_cast<const float4*>(x)
                             + (size_t)(rbase + r) * (CIN / 4);
            float4 x0 = __ldcs(xr + lane);
            float4 x1 = __ldcs(xr + lane + 32);
            float4 x2 = __ldcs(xr + lane + 64);
            float4 x3 = __ldcs(xr + lane + 96);
            // weights: L1-resident after first row (4KB total)
            float sa = (dot4(x0, __ldg(wa4 + lane))      + dot4(x1, __ldg(wa4 + lane + 32)))
                     + (dot4(x2, __ldg(wa4 + lane + 64)) + dot4(x3, __ldg(wa4 + lane + 96)));
            float sb = (dot4(x0, __ldg(wb4 + lane))      + dot4(x1, __ldg(wb4 + lane + 32)))
                     + (dot4(x2, __ldg(wb4 + lane + 64)) + dot4(x3, __ldg(wb4 + lane + 96)));
#pragma unroll
            for (int off = 16; off; off >>= 1) {
                sa += __shfl_xor_sync(0xffffffffu, sa, off);
                sb += __shfl_xor_sync(0xffffffffu, sb, off);
            }
            if (lane == 0)
                g_z[rbase + r] = make_float2(sa + biasa, sb + biasb);
        }
        __threadfence();                       // make z visible chip-wide
        __syncwarp();
        if (lane == 0)
            *(volatile unsigned int*)&g_flag[tile] = 1u;   // release
        return;
    }

    // ============================ consumer ============================
    __shared__ float2 tab[NTAB];               // (log t, log1p(-t)) * log2e
    for (int k = threadIdx.x; k < NTAB; k += 256) {
        int g = 0, off = 0;                    // grid g: 10(g+1) pts @ off
        while (k >= off + 10 * (g + 1)) { off += 10 * (g + 1); ++g; }
        int n = 10 * (g + 1);
        int j = k - off;
        float bthr = 0.1f * (float)(g + 1);
        float step = (bthr - 2.f * EPSQ) / (float)(n - 1);
        float t = fmaf(step, (float)j, EPSQ);
        tab[k] = make_float2(logf(t) * LOG2E, log1pf(-t) * LOG2E);
    }
    __syncthreads();

    const int cw = (blockIdx.x - NPRODB) * 8 + wid;      // 0..1183
    for (int tile = cw; tile < ntiles; tile += NCONSB * 8) {
        if (lane == 0) {
            while (*(volatile unsigned int*)&g_flag[tile] == 0u)
                __nanosleep(64);
            __threadfence();                   // acquire
        }
        __syncwarp();

        const int row = (tile << 5) + lane;
        float2 z = make_float2(0.f, 0.f);
        if (row < B) z = g_z[row];             // L2 hit (1MB scratch)
        __syncwarp();
        if (lane == 0)
            *(volatile unsigned int*)&g_flag[tile] = 0u;  // restore invariant
        if (row >= B) continue;

        const float za = z.x, zb = z.y;
        // stable softplus == jax.nn.softplus
        float spa = (za > 0.f) ? (za + log1pf(expf(-za))) : log1pf(expf(za));
        float spb = (zb > 0.f) ? (zb + log1pf(expf(-zb))) : log1pf(expf(zb));
        float alpha = fminf(1.f + spa, 100.f);
        float beta  = fminf(1.f + spb, 100.f);
        float lb = lgammaf(alpha) + lgammaf(beta) - lgammaf(alpha + beta);

        const float a1 = alpha - 1.f;
        const float b1 = beta - 1.f;
        const float c2 = -lb * LOG2E;          // dx & exp(-lbeta) cancel in the
                                               // normalization; keep range-safe
        float cdf[10];
        const float2* tp = tab;                // pointer-walk: reg+imm LDS
#pragma unroll
        for (int g = 0; g < 10; ++g) {
            const int n = 10 * (g + 1);
            float s0 = 0.f;
#pragma unroll 10
            for (int k = 0; k < n; ++k) {
                float2 uv = tp[k];
                s0 += ex2f(fmaf(a1, uv.x, fmaf(b1, uv.y, c2)));
            }
            cdf[g] = s0;
            tp += n;
        }

        const float inv = 1.f / cdf[9];        // telescoping total mass
        float* o = out + (size_t)row * 10;
        float prev = 0.f;
#pragma unroll
        for (int g = 0; g < 10; ++g) {
            o[g] = (cdf[g] - prev) * inv;
            prev = cdf[g];
        }
    }
}

// ---------------------------------------------------------------------------
extern "C" void kernel_launch(void* const* d_in, const int* in_sizes, int n_in,
                              void* d_out, int out_size)
{
    const float* x  = (const float*)d_in[0];
    const float* Wa = (const float*)d_in[1];
    const float* ba = (const float*)d_in[2];
    const float* Wb = (const float*)d_in[3];
    const float* bb = (const float*)d_in[4];

    int B = in_sizes[0] / CIN;
    beta_pipe<<<NPRODB + NCONSB, 256>>>(x, Wa, ba, Wb, bb, (float*)d_out, B);
}

// round 8
// speedup vs baseline: 1.0585x; 1.0585x over previous
#include <cuda_runtime.h>
#include <math.h>

#define CIN     512
#define NTAB    550            // 10+20+...+100 quadrature points
#define LOG2E   1.4426950408889634f
#define EPSQ    1e-5f
#define NBLK    296            // 2 blocks/SM on 148 SMs
#define NTHR    256            // 8 warps/block -> 2368 warps total

__device__ __forceinline__ float ex2f(float x) {
    float r;
    asm("ex2.approx.f32 %0, %1;" : "=f"(r) : "f"(x));
    return r;
}
__device__ __forceinline__ float dot4(float4 a, float4 b) {
    return fmaf(a.x, b.x, fmaf(a.y, b.y, fmaf(a.z, b.z, a.w * b.w)));
}

// ---------------------------------------------------------------------------
// Independent-warp A/B-alternating kernel. Each warp loops over 32-row tiles
// (grid-stride). Per tile:
//   Phase A: warp-per-row dual GEMV; lane r keeps row r's logits in regs.
//   Phase B: thread-per-row Beta quadrature over the shared 550-pt table.
// No inter-warp coupling at all: after the first tile, DRAM-service jitter
// de-phases the ~16 resident warps/SM, so at any time some warps stream x
// from DRAM (phase A) while others issue ex2.approx (phase B). Steady state
// approaches max(DRAM 40us, MUFU 17us) instead of their sum.
// ---------------------------------------------------------------------------
__global__ void __launch_bounds__(NTHR)
fused_beta_kernel(const float* __restrict__ x,
                  const float* __restrict__ Wa, const float* __restrict__ ba,
                  const float* __restrict__ Wb, const float* __restrict__ bb,
                  float* __restrict__ out, int B)
{
    __shared__ float2 tab[NTAB];       // (log t, log1p(-t)) * log2e

    const int tid  = threadIdx.x;
    const int lane = tid & 31;

    // ---- build quadrature table (row-independent) ----
    for (int k = tid; k < NTAB; k += NTHR) {
        int g = 0, off = 0;                       // grid g: 10(g+1) pts @ off
        while (k >= off + 10 * (g + 1)) { off += 10 * (g + 1); ++g; }
        int n = 10 * (g + 1);
        int j = k - off;
        float bthr = 0.1f * (float)(g + 1);
        float step = (bthr - 2.f * EPSQ) / (float)(n - 1);
        float t = fmaf(step, (float)j, EPSQ);
        tab[k] = make_float2(logf(t) * LOG2E, log1pf(-t) * LOG2E);
    }
    __syncthreads();                  // only sync in the kernel

    // ---- hoist weights into registers (L1-fed, 4KB total) ----
    const float4* wa4 = reinterpret_cast<const float4*>(Wa);
    const float4* wb4 = reinterpret_cast<const float4*>(Wb);
    const float4 av0 = __ldg(wa4 + lane),      av1 = __ldg(wa4 + lane + 32);
    const float4 av2 = __ldg(wa4 + lane + 64), av3 = __ldg(wa4 + lane + 96);
    const float4 bv0 = __ldg(wb4 + lane),      bv1 = __ldg(wb4 + lane + 32);
    const float4 bv2 = __ldg(wb4 + lane + 64), bv3 = __ldg(wb4 + lane + 96);
    const float biasa = ba[0], biasb = bb[0];

    const int ntiles = (B + 31) >> 5;
    const int nwarps = NBLK * (NTHR >> 5);
    const int gwarp  = blockIdx.x * (NTHR >> 5) + (tid >> 5);

    for (int tile = gwarp; tile < ntiles; tile += nwarps) {
        const int base = tile << 5;

        // ================= phase A: dual GEMV, 32 rows =================
        float za = 0.f, zb = 0.f;     // row 'lane' logits land here
        const int rlim = min(32, B - base);
#pragma unroll 2
        for (int r = 0; r < rlim; ++r) {
            const float4* xr = reinterpret_cast<const float4*>(x)
                             + (size_t)(base + r) * (CIN / 4);
            float4 x0 = __ldcs(xr + lane);
            float4 x1 = __ldcs(xr + lane + 32);
            float4 x2 = __ldcs(xr + lane + 64);
            float4 x3 = __ldcs(xr + lane + 96);
            float sa = (dot4(x0, av0) + dot4(x1, av1))
                     + (dot4(x2, av2) + dot4(x3, av3));
            float sb = (dot4(x0, bv0) + dot4(x1, bv1))
                     + (dot4(x2, bv2) + dot4(x3, bv3));
#pragma unroll
            for (int off = 16; off; off >>= 1) {
                sa += __shfl_xor_sync(0xffffffffu, sa, off);
                sb += __shfl_xor_sync(0xffffffffu, sb, off);
            }
            if (lane == r) { za = sa + biasa; zb = sb + biasb; }
        }

        // ================= phase B: quadrature, row = base+lane ========
        const int row = base + lane;
        if (row >= B) continue;

        // stable softplus == jax.nn.softplus
        float spa = (za > 0.f) ? (za + log1pf(expf(-za))) : log1pf(expf(za));
        float spb = (zb > 0.f) ? (zb + log1pf(expf(-zb))) : log1pf(expf(zb));
        float alpha = fminf(1.f + spa, 100.f);
        float beta  = fminf(1.f + spb, 100.f);
        float lb = lgammaf(alpha) + lgammaf(beta) - lgammaf(alpha + beta);

        const float a1 = alpha - 1.f;
        const float b1 = beta - 1.f;
        const float c2 = -lb * LOG2E;  // dx & exp(-lbeta) cancel in the row
                                       // normalization; keep exponent in range
        float cdf[10];
        const float2* tp = tab;        // pointer-walk: reg+imm LDS addressing
#pragma unroll
        for (int g = 0; g < 10; ++g) {
            const int n = 10 * (g + 1);
            float s0 = 0.f;
#pragma unroll 10
            for (int k = 0; k < n; ++k) {
                float2 uv = tp[k];
                s0 += ex2f(fmaf(a1, uv.x, fmaf(b1, uv.y, c2)));
            }
            cdf[g] = s0;
            tp += n;
        }

        const float inv = 1.f / cdf[9];           // telescoping total mass
        float* o = out + (size_t)row * 10;
        float prev = 0.f;
#pragma unroll
        for (int g = 0; g < 10; ++g) {
            o[g] = (cdf[g] - prev) * inv;
            prev = cdf[g];
        }
    }
}

// ---------------------------------------------------------------------------
extern "C" void kernel_launch(void* const* d_in, const int* in_sizes, int n_in,
                              void* d_out, int out_size)
{
    const float* x  = (const float*)d_in[0];
    const float* Wa = (const float*)d_in[1];
    const float* ba = (const float*)d_in[2];
    const float* Wb = (const float*)d_in[3];
    const float* bb = (const float*)d_in[4];

    int B = in_sizes[0] / CIN;
    fused_beta_kernel<<<NBLK, NTHR>>>(x, Wa, ba, Wb, bb, (float*)d_out, B);
}

// round 12
// speedup vs baseline: 1.5931x; 1.5050x over previous
#include <cuda_runtime.h>
#include <math.h>

#define CIN     512
#define NTAB    550            // 10+20+...+100 quadrature points
#define LOG2E   1.4426950408889634f
#define EPSQ    1e-5f
#define NTHR    768            // 24 warps: 16 producer + 8 consumer
#define PWARPS  16
#define RPI     256            // rows per iteration (= consumer lanes)
#define NBLK    152            // one block per SM (GB300: 152 SMs)

__device__ __forceinline__ float ex2f(float x) {
    float r;
    asm("ex2.approx.f32 %0, %1;" : "=f"(r) : "f"(x));
    return r;
}
__device__ __forceinline__ float dot4(float4 a, float4 b) {
    return fmaf(a.x, b.x, fmaf(a.y, b.y, fmaf(a.z, b.z, a.w * b.w)));
}

// ---------------------------------------------------------------------------
// Split-block software pipeline, one 768-thread block per SM.
//   warps 0-15 : producers. Iter i: dual GEMV for 256 rows (16 rows/warp,
//                warp-per-row) -> zbuf[i&1]. DRAM-bound.
//   warps 16-23: consumers. Iter i: Beta quadrature for the 256 rows of
//                iter i-1 from zbuf[(i-1)&1] (one row per lane). MUFU-bound.
// One __syncthreads per iteration; double buffering means producers write
// buffer p while consumers read buffer 1-p. In steady state each SM streams
// 512KB from DRAM and issues 140K ex2 ops CONCURRENTLY, so the MUFU phase
// (~4.6us/iter) hides entirely under the DRAM phase (~11.5us/iter).
// ---------------------------------------------------------------------------
__global__ void __launch_bounds__(NTHR)
beta_pipe_kernel(const float* __restrict__ x,
                 const float* __restrict__ Wa, const float* __restrict__ ba,
                 const float* __restrict__ Wb, const float* __restrict__ bb,
                 float* __restrict__ out, int B)
{
    __shared__ float2 tab[NTAB];        // (log t, log1p(-t)) * log2e
    __shared__ float2 zbuf[2][RPI];     // double-buffered logits handoff

    const int tid  = threadIdx.x;
    const int lane = tid & 31;
    const int wid  = tid >> 5;

    // ---- build quadrature table (row-independent) ----
    for (int k = tid; k < NTAB; k += NTHR) {
        int g = 0, off = 0;                        // grid g: 10(g+1) pts @ off
        while (k >= off + 10 * (g + 1)) { off += 10 * (g + 1); ++g; }
        int n = 10 * (g + 1);
        int j = k - off;
        float bthr = 0.1f * (float)(g + 1);
        float step = (bthr - 2.f * EPSQ) / (float)(n - 1);
        float t = fmaf(step, (float)j, EPSQ);
        tab[k] = make_float2(logf(t) * LOG2E, log1pf(-t) * LOG2E);
    }
    __syncthreads();

    const int rowsPB     = (B + NBLK - 1) / NBLK;        // rows per block
    const int blockStart = blockIdx.x * rowsPB;
    const int nIter      = (rowsPB + RPI - 1) / RPI;     // uniform across blocks

    // producer-only register state (weights; 4KB, L1-backed)
    float4 av0, av1, av2, av3, bv0, bv1, bv2, bv3;
    float biasa = 0.f, biasb = 0.f;
    if (wid < PWARPS) {
        const float4* wa4 = reinterpret_cast<const float4*>(Wa);
        const float4* wb4 = reinterpret_cast<const float4*>(Wb);
        av0 = __ldg(wa4 + lane);      av1 = __ldg(wa4 + lane + 32);
        av2 = __ldg(wa4 + lane + 64); av3 = __ldg(wa4 + lane + 96);
        bv0 = __ldg(wb4 + lane);      bv1 = __ldg(wb4 + lane + 32);
        bv2 = __ldg(wb4 + lane + 64); bv3 = __ldg(wb4 + lane + 96);
        biasa = ba[0]; biasb = bb[0];
    }

    for (int it = 0; it <= nIter; ++it) {
        if (wid < PWARPS) {
            // ======================= producer =======================
            if (it < nIter) {
                const int rb = blockStart + it * RPI + wid * 16;
#pragma unroll 1
                for (int r = 0; r < 16; ++r) {
                    const int row = rb + r;
                    float sa = 0.f, sb = 0.f;
                    if (row < B) {
                        const float4* xr = reinterpret_cast<const float4*>(x)
                                         + (size_t)row * (CIN / 4);
                        float4 x0 = __ldcs(xr + lane);
                        float4 x1 = __ldcs(xr + lane + 32);
                        float4 x2 = __ldcs(xr + lane + 64);
                        float4 x3 = __ldcs(xr + lane + 96);
                        sa = (dot4(x0, av0) + dot4(x1, av1))
                           + (dot4(x2, av2) + dot4(x3, av3));
                        sb = (dot4(x0, bv0) + dot4(x1, bv1))
                           + (dot4(x2, bv2) + dot4(x3, bv3));
                    }
#pragma unroll
                    for (int off = 16; off; off >>= 1) {
                        sa += __shfl_xor_sync(0xffffffffu, sa, off);
                        sb += __shfl_xor_sync(0xffffffffu, sb, off);
                    }
                    if (lane == 0)
                        zbuf[it & 1][wid * 16 + r] =
                            make_float2(sa + biasa, sb + biasb);
                }
            }
        } else if (it > 0) {
            // ======================= consumer =======================
            const int idx = (wid - PWARPS) * 32 + lane;          // 0..255
            const int row = blockStart + (it - 1) * RPI + idx;
            if (row < B) {
                const float2 z = zbuf[(it - 1) & 1][idx];
                const float za = z.x, zb = z.y;
                // stable softplus == jax.nn.softplus
                float spa = (za > 0.f) ? (za + log1pf(expf(-za)))
                                       : log1pf(expf(za));
                float spb = (zb > 0.f) ? (zb + log1pf(expf(-zb)))
                                       : log1pf(expf(zb));
                float alpha = fminf(1.f + spa, 100.f);
                float beta  = fminf(1.f + spb, 100.f);
                float lb = lgammaf(alpha) + lgammaf(beta)
                         - lgammaf(alpha + beta);

                const float a1 = alpha - 1.f;
                const float b1 = beta - 1.f;
                const float c2 = -lb * LOG2E;  // dx & exp(-lbeta) cancel in the
                                               // normalization; keep range-safe
                float cdf[10];
                const float2* tp = tab;        // pointer-walk: reg+imm LDS
#pragma unroll
                for (int g = 0; g < 10; ++g) {
                    const int n = 10 * (g + 1);
                    float s0 = 0.f;
#pragma unroll 10
                    for (int k = 0; k < n; ++k) {
                        float2 uv = tp[k];
                        s0 += ex2f(fmaf(a1, uv.x, fmaf(b1, uv.y, c2)));
                    }
                    cdf[g] = s0;
                    tp += n;
                }

                const float inv = 1.f / cdf[9];     // telescoping total mass
                float* o = out + (size_t)row * 10;
                float prev = 0.f;
#pragma unroll
                for (int g = 0; g < 10; ++g) {
                    o[g] = (cdf[g] - prev) * inv;
                    prev = cdf[g];
                }
            }
        }
        __syncthreads();    // all 24 warps, both roles, every iteration
    }
}

// ---------------------------------------------------------------------------
extern "C" void kernel_launch(void* const* d_in, const int* in_sizes, int n_in,
                              void* d_out, int out_size)
{
    const float* x  = (const float*)d_in[0];
    const float* Wa = (const float*)d_in[1];
    const float* ba = (const float*)d_in[2];
    const float* Wb = (const float*)d_in[3];
    const float* bb = (const float*)d_in[4];

    int B = in_sizes[0] / CIN;
    beta_pipe_kernel<<<NBLK, NTHR>>>(x, Wa, ba, Wb, bb, (float*)d_out, B);
}